// round 3
// baseline (speedup 1.0000x reference)
#include <cuda_runtime.h>
#include <math.h>
#include <float.h>

#define B    64
#define P    196
#define ENC  2048
#define H    512
#define E    512
#define A_DIM 512
#define V    30000
#define T    20

// ---------------- scratch (device globals, no allocations) ----------------
__device__ __align__(128) float g_att_enc[B * P * A_DIM];   // 25.7 MB
__device__ __align__(128) float g_mean[B * ENC];
__device__ __align__(128) float g_h[B * H];
__device__ __align__(128) float g_c[B * H];
__device__ __align__(128) float g_atth[B * A_DIM];
__device__ __align__(128) float g_scores[B * P];            // reused as alpha
__device__ __align__(128) float g_weighted[B * ENC];
__device__ __align__(128) float g_gate[B * ENC];
__device__ __align__(128) float g_inp[B * (E + ENC)];
__device__ __align__(128) float g_gates[B * 4 * H];

__device__ __forceinline__ float sigm(float x) { return 1.f / (1.f + expf(-x)); }

// ---------------- generic fp32 GEMM: C[M,N] = A[M,K] @ W[N,K]^T (+bias)(+=C) --
// BM=64, BN=64, BK=16, 256 threads, 4x4 register tile per thread.
// AOP: 0 = identity, 1 = sigmoid applied to A elements.
// M must be a multiple of 64 (true for all call sites); N bounds-checked.
template <int AOP, bool ACC>
__global__ void __launch_bounds__(256) sgemm_k(
    const float* __restrict__ Am, int lda,
    const float* __restrict__ Wm,
    const float* __restrict__ bias,
    float* __restrict__ C, long long ldc,
    int K, int N)
{
    __shared__ float As[16][64];
    __shared__ float Ws[16][64];

    const int tid  = threadIdx.x;
    const int tx   = tid & 15;        // n-tile position
    const int ty   = tid >> 4;        // m-tile position
    const int arow = tid >> 2;        // 0..63 (row loaded by this thread)
    const int kc   = (tid & 3) << 2;  // 0,4,8,12 (k sub-column)

    const int m0 = blockIdx.y * 64;
    const int n0 = blockIdx.x * 64;
    const int wrow = n0 + arow;

    const float* Aptr = Am + (size_t)(m0 + arow) * lda + kc;
    const float* Wptr = (wrow < N) ? (Wm + (size_t)wrow * K + kc) : nullptr;

    float acc[4][4];
#pragma unroll
    for (int i = 0; i < 4; i++)
#pragma unroll
        for (int j = 0; j < 4; j++) acc[i][j] = 0.f;

    for (int k0 = 0; k0 < K; k0 += 16) {
        float4 av = *(const float4*)(Aptr + k0);
        float4 wv = Wptr ? *(const float4*)(Wptr + k0) : make_float4(0.f, 0.f, 0.f, 0.f);
        if (AOP == 1) {
            av.x = sigm(av.x); av.y = sigm(av.y);
            av.z = sigm(av.z); av.w = sigm(av.w);
        }
        __syncthreads();   // previous compute done before overwriting smem
        As[kc + 0][arow] = av.x; As[kc + 1][arow] = av.y;
        As[kc + 2][arow] = av.z; As[kc + 3][arow] = av.w;
        Ws[kc + 0][arow] = wv.x; Ws[kc + 1][arow] = wv.y;
        Ws[kc + 2][arow] = wv.z; Ws[kc + 3][arow] = wv.w;
        __syncthreads();

#pragma unroll
        for (int kk = 0; kk < 16; kk++) {
            float4 a = *(const float4*)&As[kk][ty << 2];
            float4 w = *(const float4*)&Ws[kk][tx << 2];
            acc[0][0] += a.x * w.x; acc[0][1] += a.x * w.y; acc[0][2] += a.x * w.z; acc[0][3] += a.x * w.w;
            acc[1][0] += a.y * w.x; acc[1][1] += a.y * w.y; acc[1][2] += a.y * w.z; acc[1][3] += a.y * w.w;
            acc[2][0] += a.z * w.x; acc[2][1] += a.z * w.y; acc[2][2] += a.z * w.z; acc[2][3] += a.z * w.w;
            acc[3][0] += a.w * w.x; acc[3][1] += a.w * w.y; acc[3][2] += a.w * w.z; acc[3][3] += a.w * w.w;
        }
    }

#pragma unroll
    for (int i = 0; i < 4; i++) {
        const int m = m0 + (ty << 2) + i;
#pragma unroll
        for (int j = 0; j < 4; j++) {
            const int n = n0 + (tx << 2) + j;
            if (n < N) {
                float v = acc[i][j];
                if (ACC) v += C[(size_t)m * ldc + n];
                if (bias) v += bias[n];
                C[(size_t)m * ldc + n] = v;
            }
        }
    }
}

// ---------------- mean over P ----------------
__global__ void mean_k(const float* __restrict__ enc)
{
    const int idx = blockIdx.x * 256 + threadIdx.x;   // B*ENC
    const int b = idx >> 11;
    const int e = idx & (ENC - 1);
    const float* p = enc + (size_t)b * P * ENC + e;
    float s = 0.f;
    for (int pp = 0; pp < P; pp++) s += p[(size_t)pp * ENC];
    g_mean[idx] = s * (1.f / (float)P);
}

// ---------------- attention scores: relu(att_enc + att_h) . Wa + ba --------
__global__ void scores_k(const float* __restrict__ Wa, const float* __restrict__ ba)
{
    __shared__ float sh_h[A_DIM];
    __shared__ float sh_w[A_DIM];
    const int b = blockIdx.x;
    const int tid = threadIdx.x;
    for (int i = tid; i < A_DIM; i += 256) {
        sh_h[i] = g_atth[b * A_DIM + i];
        sh_w[i] = Wa[i];
    }
    __syncthreads();
    const int w = tid >> 5, lane = tid & 31;
    const int p = blockIdx.y * 8 + w;
    if (p < P) {
        const float* row = g_att_enc + (size_t)(b * P + p) * A_DIM;
        float s = 0.f;
#pragma unroll 4
        for (int a = lane; a < A_DIM; a += 32) {
            float v = row[a] + sh_h[a];
            s += fmaxf(v, 0.f) * sh_w[a];
        }
#pragma unroll
        for (int off = 16; off; off >>= 1) s += __shfl_xor_sync(0xffffffff, s, off);
        if (lane == 0) g_scores[b * P + p] = s + ba[0];
    }
}

// ---------------- softmax over P (in place into g_scores) ------------------
__global__ void softmax_k()
{
    __shared__ float sh[256];
    const int b = blockIdx.x, tid = threadIdx.x;
    const float v = (tid < P) ? g_scores[b * P + tid] : -FLT_MAX;
    sh[tid] = v;
    __syncthreads();
    for (int off = 128; off; off >>= 1) {
        if (tid < off) sh[tid] = fmaxf(sh[tid], sh[tid + off]);
        __syncthreads();
    }
    const float mx = sh[0];
    __syncthreads();
    const float e = (tid < P) ? expf(v - mx) : 0.f;
    sh[tid] = e;
    __syncthreads();
    for (int off = 128; off; off >>= 1) {
        if (tid < off) sh[tid] += sh[tid + off];
        __syncthreads();
    }
    const float inv = 1.f / sh[0];
    if (tid < P) g_scores[b * P + tid] = e * inv;
}

// ---------------- weighted = alpha @ encode_out ----------------------------
__global__ void weighted_k(const float* __restrict__ enc)
{
    __shared__ float sa[P];
    const int b = blockIdx.y;
    const int e = blockIdx.x * 256 + threadIdx.x;
    if (threadIdx.x < P) sa[threadIdx.x] = g_scores[b * P + threadIdx.x];
    __syncthreads();
    const float* base = enc + (size_t)b * P * ENC + e;
    float s = 0.f;
#pragma unroll 4
    for (int p = 0; p < P; p++) s += sa[p] * base[(size_t)p * ENC];
    g_weighted[b * ENC + e] = s;
}

// ---------------- build LSTM input [x_t , weighted*gate] -------------------
__global__ void inp_k(const float* __restrict__ emb, const int* __restrict__ cap, int t)
{
    const int idx = blockIdx.x * 256 + threadIdx.x;   // B*(E+ENC)
    const int b = idx / (E + ENC);
    const int j = idx - b * (E + ENC);
    float v;
    if (j < E) {
        const int tok = cap[b * T + t];
        v = emb[(size_t)tok * E + j];
    } else {
        const int j2 = j - E;
        v = g_weighted[b * ENC + j2] * g_gate[b * ENC + j2];
    }
    g_inp[idx] = v;
}

// ---------------- LSTM cell ----------------
__global__ void lstm_k()
{
    const int idx = blockIdx.x * 256 + threadIdx.x;   // B*H
    const int b = idx >> 9;
    const int n = idx & (H - 1);
    const float* g = g_gates + b * 4 * H;
    const float i_ = sigm(g[n]);
    const float f_ = sigm(g[H + n]);
    const float gg = tanhf(g[2 * H + n]);
    const float o_ = sigm(g[3 * H + n]);
    const float c  = f_ * g_c[idx] + i_ * gg;
    g_c[idx] = c;
    g_h[idx] = o_ * tanhf(c);
}

// ---------------- zero the final time step ----------------
__global__ void zero_k(float* __restrict__ out)
{
    const int idx = blockIdx.x * 256 + threadIdx.x;
    if (idx < B * V) {
        const int b = idx / V;
        const int n = idx - b * V;
        out[(size_t)b * T * V + (size_t)(T - 1) * V + n] = 0.f;
    }
}

// ---------------- launch ----------------
extern "C" void kernel_launch(void* const* d_in, const int* in_sizes, int n_in,
                              void* d_out, int out_size)
{
    const float* enc  = (const float*)d_in[0];
    const int*   cap  = (const int*)d_in[1];
    const float* emb  = (const float*)d_in[2];
    const float* W_ih = (const float*)d_in[3];
    const float* b_ih = (const float*)d_in[4];
    const float* W_hh = (const float*)d_in[5];
    const float* b_hh = (const float*)d_in[6];
    const float* We   = (const float*)d_in[7];
    const float* be   = (const float*)d_in[8];
    const float* Wh   = (const float*)d_in[9];
    const float* bh   = (const float*)d_in[10];
    const float* Wa   = (const float*)d_in[11];
    const float* ba   = (const float*)d_in[12];
    const float* Wch  = (const float*)d_in[13];
    const float* bch  = (const float*)d_in[14];
    const float* Wcc  = (const float*)d_in[15];
    const float* bcc  = (const float*)d_in[16];
    const float* Wfc  = (const float*)d_in[17];
    const float* bfc  = (const float*)d_in[18];
    const float* Wg   = (const float*)d_in[19];
    const float* bg   = (const float*)d_in[20];
    float* out = (float*)d_out;

    float *p_att_enc, *p_mean, *p_h, *p_c, *p_atth, *p_inp, *p_gates, *p_gate;
    cudaGetSymbolAddress((void**)&p_att_enc, g_att_enc);
    cudaGetSymbolAddress((void**)&p_mean,    g_mean);
    cudaGetSymbolAddress((void**)&p_h,       g_h);
    cudaGetSymbolAddress((void**)&p_c,       g_c);
    cudaGetSymbolAddress((void**)&p_atth,    g_atth);
    cudaGetSymbolAddress((void**)&p_inp,     g_inp);
    cudaGetSymbolAddress((void**)&p_gates,   g_gates);
    cudaGetSymbolAddress((void**)&p_gate,    g_gate);

    // mean over P
    mean_k<<<(B * ENC) / 256, 256>>>(enc);
    // h0 = mean @ Wch^T + bch ; c0 = mean @ Wcc^T + bcc
    sgemm_k<0, false><<<dim3(H / 64, 1), 256>>>(p_mean, ENC, Wch, bch, p_h, H, ENC, H);
    sgemm_k<0, false><<<dim3(H / 64, 1), 256>>>(p_mean, ENC, Wcc, bcc, p_c, H, ENC, H);
    // att_enc = encode_out @ We^T + be   (one-time, M = B*P = 12544)
    sgemm_k<0, false><<<dim3(A_DIM / 64, (B * P) / 64), 256>>>(
        enc, ENC, We, be, p_att_enc, A_DIM, ENC, A_DIM);

    for (int t = 0; t < T - 1; t++) {
        // att_h = h @ Wh^T + bh
        sgemm_k<0, false><<<dim3(A_DIM / 64, 1), 256>>>(p_h, H, Wh, bh, p_atth, A_DIM, H, A_DIM);
        // scores + softmax + weighted sum
        scores_k<<<dim3(B, (P + 7) / 8), 256>>>(Wa, ba);
        softmax_k<<<B, 256>>>();
        weighted_k<<<dim3(ENC / 256, B), 256>>>(enc);
        // gate = sigmoid(h) @ Wg^T + bg
        sgemm_k<1, false><<<dim3(ENC / 64, 1), 256>>>(p_h, H, Wg, bg, p_gate, ENC, H, ENC);
        // inp = [x_t , weighted*gate]
        inp_k<<<(B * (E + ENC)) / 256, 256>>>(emb, cap, t);
        // gates = inp @ W_ih^T + b_ih + h @ W_hh^T + b_hh
        sgemm_k<0, false><<<dim3((4 * H) / 64, 1), 256>>>(p_inp, E + ENC, W_ih, b_ih, p_gates, 4 * H, E + ENC, 4 * H);
        sgemm_k<0, true ><<<dim3((4 * H) / 64, 1), 256>>>(p_h, H, W_hh, b_hh, p_gates, 4 * H, H, 4 * H);
        // LSTM cell -> h,c updated in place
        lstm_k<<<(B * H) / 256, 256>>>();
        // pred = h_new @ Wfc^T + bfc  -> out[:, t, :]
        sgemm_k<0, false><<<dim3((V + 63) / 64, 1), 256>>>(
            p_h, H, Wfc, bfc, out + (size_t)t * V, (long long)T * V, H, V);
    }
    // out[:, T-1, :] = 0
    zero_k<<<(B * V + 255) / 256, 256>>>(out);
}

// round 4
// speedup vs baseline: 2.6657x; 2.6657x over previous
#include <cuda_runtime.h>
#include <math.h>
#include <float.h>

#define B    64
#define P    196
#define ENC  2048
#define H    512
#define E    512
#define A_DIM 512
#define V    30000
#define T    20

#define NS_HC    8   // h0/c0 split-K  (chunk 256, K=2048)
#define NS_ATTH  8   // att_h split-K  (chunk 64,  K=512)
#define NS_GATE  4   // gate split-K   (chunk 128, K=512)
#define NS_GATES 12  // gates split-K  (chunk 256, K=3072)

// ---------------- scratch (device globals, no allocations) ----------------
__device__ __align__(128) float g_att_enc[B * P * A_DIM];          // 25.7 MB
__device__ __align__(128) float g_part[NS_GATES * B * 4 * H];      // 6 MB, reused by all split-K gemms
__device__ __align__(128) float g_mean[B * ENC];
__device__ __align__(128) float g_h[B * H];
__device__ __align__(128) float g_c[B * H];
__device__ __align__(128) float g_alpha[B * P];
__device__ __align__(128) float g_weighted[B * ENC];
__device__ __align__(128) float g_inp[B * (E + ENC)];

__device__ __forceinline__ float sigm(float x) { return 1.f / (1.f + expf(-x)); }

// =====================================================================
// gemm64: C(part)[M=64, N-tile=64] , 128 threads, 8x4 microtile, BK=16.
// Split-K over blockIdx.y: block handles k in [s*kchunk, (s+1)*kchunk).
// MODE 0 = plain A, 1 = sigmoid(A), 2 = dual region (A1/W1 for k<K1, A2/W2 after).
// Partial output: C + s*64*ldc (for splits ldc=N, bias=null).
// =====================================================================
template <int MODE>
__global__ void __launch_bounds__(128) gemm64_k(
    const float* __restrict__ A1, int lda1,
    const float* __restrict__ A2, int lda2,
    const float* __restrict__ W1, int ldw1,
    const float* __restrict__ W2, int ldw2, int K1,
    const float* __restrict__ bias,
    float* __restrict__ C, long long ldc, int N, int kchunk)
{
    __shared__ float As[16][64];
    __shared__ float Ws[16][64];

    const int tid = threadIdx.x;
    const int n0  = blockIdx.x * 64;
    const int s   = blockIdx.y;
    const int k0b = s * kchunk;

    const float* Abase; int ldA;
    const float* Wbase; int ldW;
    if (MODE == 2 && k0b >= K1) {
        Abase = A2 + (k0b - K1); ldA = lda2;
        Wbase = W2 + (k0b - K1); ldW = ldw2;
    } else {
        Abase = A1 + k0b; ldA = lda1;
        Wbase = W1 + k0b; ldW = ldw1;
    }

    // loader indices
    const int lr = tid & 63;          // row within tile
    const int lk = (tid >> 6) * 8;    // k offset 0 or 8
    const int wrow = n0 + lr;
    const float* Ap = Abase + (size_t)lr * ldA + lk;
    const float* Wp = (wrow < N) ? (Wbase + (size_t)wrow * ldW + lk) : nullptr;

    // compute indices
    const int tx = tid & 15;          // col group (4 cols)
    const int ty = tid >> 4;          // row group (8 rows)

    float acc[8][4];
#pragma unroll
    for (int i = 0; i < 8; i++)
#pragma unroll
        for (int j = 0; j < 4; j++) acc[i][j] = 0.f;

    for (int kk0 = 0; kk0 < kchunk; kk0 += 16) {
        float4 a0 = *(const float4*)(Ap + kk0);
        float4 a1 = *(const float4*)(Ap + kk0 + 4);
        float4 w0, w1;
        if (Wp) { w0 = *(const float4*)(Wp + kk0); w1 = *(const float4*)(Wp + kk0 + 4); }
        else    { w0 = make_float4(0,0,0,0); w1 = w0; }
        if (MODE == 1) {
            a0.x = sigm(a0.x); a0.y = sigm(a0.y); a0.z = sigm(a0.z); a0.w = sigm(a0.w);
            a1.x = sigm(a1.x); a1.y = sigm(a1.y); a1.z = sigm(a1.z); a1.w = sigm(a1.w);
        }
        __syncthreads();
        As[lk + 0][lr] = a0.x; As[lk + 1][lr] = a0.y; As[lk + 2][lr] = a0.z; As[lk + 3][lr] = a0.w;
        As[lk + 4][lr] = a1.x; As[lk + 5][lr] = a1.y; As[lk + 6][lr] = a1.z; As[lk + 7][lr] = a1.w;
        Ws[lk + 0][lr] = w0.x; Ws[lk + 1][lr] = w0.y; Ws[lk + 2][lr] = w0.z; Ws[lk + 3][lr] = w0.w;
        Ws[lk + 4][lr] = w1.x; Ws[lk + 5][lr] = w1.y; Ws[lk + 6][lr] = w1.z; Ws[lk + 7][lr] = w1.w;
        __syncthreads();

#pragma unroll
        for (int kk = 0; kk < 16; kk++) {
            float4 ra0 = *(const float4*)&As[kk][ty * 8];
            float4 ra1 = *(const float4*)&As[kk][ty * 8 + 4];
            float4 rw  = *(const float4*)&Ws[kk][tx * 4];
            acc[0][0] += ra0.x * rw.x; acc[0][1] += ra0.x * rw.y; acc[0][2] += ra0.x * rw.z; acc[0][3] += ra0.x * rw.w;
            acc[1][0] += ra0.y * rw.x; acc[1][1] += ra0.y * rw.y; acc[1][2] += ra0.y * rw.z; acc[1][3] += ra0.y * rw.w;
            acc[2][0] += ra0.z * rw.x; acc[2][1] += ra0.z * rw.y; acc[2][2] += ra0.z * rw.z; acc[2][3] += ra0.z * rw.w;
            acc[3][0] += ra0.w * rw.x; acc[3][1] += ra0.w * rw.y; acc[3][2] += ra0.w * rw.z; acc[3][3] += ra0.w * rw.w;
            acc[4][0] += ra1.x * rw.x; acc[4][1] += ra1.x * rw.y; acc[4][2] += ra1.x * rw.z; acc[4][3] += ra1.x * rw.w;
            acc[5][0] += ra1.y * rw.x; acc[5][1] += ra1.y * rw.y; acc[5][2] += ra1.y * rw.z; acc[5][3] += ra1.y * rw.w;
            acc[6][0] += ra1.z * rw.x; acc[6][1] += ra1.z * rw.y; acc[6][2] += ra1.z * rw.z; acc[6][3] += ra1.z * rw.w;
            acc[7][0] += ra1.w * rw.x; acc[7][1] += ra1.w * rw.y; acc[7][2] += ra1.w * rw.z; acc[7][3] += ra1.w * rw.w;
        }
    }

    float* Cb = C + (size_t)s * 64 * ldc;
#pragma unroll
    for (int i = 0; i < 8; i++) {
        const int m = ty * 8 + i;
        const int n = n0 + tx * 4;
        if (n < N) {   // N % 4 == 0 at all call sites, so full float4 is valid
            float4 v = make_float4(acc[i][0], acc[i][1], acc[i][2], acc[i][3]);
            if (bias) {
                const float4 bv = *(const float4*)(bias + n);
                v.x += bv.x; v.y += bv.y; v.z += bv.z; v.w += bv.w;
            }
            *(float4*)(Cb + (size_t)m * ldc + n) = v;
        }
    }
}

// =====================================================================
// gemm_big: 128x128 tile, 256 threads, 8x8 microtile — att_enc only.
// C[M,512] = A[M,2048] @ W[512,2048]^T + bias.  M=12544, grid (4, 98).
// =====================================================================
__global__ void __launch_bounds__(256, 2) gemm_big_k(
    const float* __restrict__ Am,
    const float* __restrict__ Wm,
    const float* __restrict__ bias,
    float* __restrict__ C)
{
    __shared__ float As[16][128];
    __shared__ float Ws[16][128];

    const int tid = threadIdx.x;
    const int n0 = blockIdx.x * 128;
    const int m0 = blockIdx.y * 128;

    const int lr = tid & 127;
    const int lk = (tid >> 7) * 8;
    const float* Ap = Am + (size_t)(m0 + lr) * ENC + lk;
    const float* Wp = Wm + (size_t)(n0 + lr) * ENC + lk;

    const int tx = tid & 15;   // 8 cols
    const int ty = tid >> 4;   // 8 rows

    float acc[8][8];
#pragma unroll
    for (int i = 0; i < 8; i++)
#pragma unroll
        for (int j = 0; j < 8; j++) acc[i][j] = 0.f;

    for (int k0 = 0; k0 < ENC; k0 += 16) {
        float4 a0 = *(const float4*)(Ap + k0);
        float4 a1 = *(const float4*)(Ap + k0 + 4);
        float4 w0 = *(const float4*)(Wp + k0);
        float4 w1 = *(const float4*)(Wp + k0 + 4);
        __syncthreads();
        As[lk + 0][lr] = a0.x; As[lk + 1][lr] = a0.y; As[lk + 2][lr] = a0.z; As[lk + 3][lr] = a0.w;
        As[lk + 4][lr] = a1.x; As[lk + 5][lr] = a1.y; As[lk + 6][lr] = a1.z; As[lk + 7][lr] = a1.w;
        Ws[lk + 0][lr] = w0.x; Ws[lk + 1][lr] = w0.y; Ws[lk + 2][lr] = w0.z; Ws[lk + 3][lr] = w0.w;
        Ws[lk + 4][lr] = w1.x; Ws[lk + 5][lr] = w1.y; Ws[lk + 6][lr] = w1.z; Ws[lk + 7][lr] = w1.w;
        __syncthreads();

#pragma unroll
        for (int kk = 0; kk < 16; kk++) {
            float4 ra0 = *(const float4*)&As[kk][ty * 8];
            float4 ra1 = *(const float4*)&As[kk][ty * 8 + 4];
            float4 rw0 = *(const float4*)&Ws[kk][tx * 8];
            float4 rw1 = *(const float4*)&Ws[kk][tx * 8 + 4];
            const float aval[8] = {ra0.x, ra0.y, ra0.z, ra0.w, ra1.x, ra1.y, ra1.z, ra1.w};
            const float wval[8] = {rw0.x, rw0.y, rw0.z, rw0.w, rw1.x, rw1.y, rw1.z, rw1.w};
#pragma unroll
            for (int i = 0; i < 8; i++)
#pragma unroll
                for (int j = 0; j < 8; j++) acc[i][j] += aval[i] * wval[j];
        }
    }

#pragma unroll
    for (int i = 0; i < 8; i++) {
        const int m = m0 + ty * 8 + i;
#pragma unroll
        for (int jj = 0; jj < 2; jj++) {
            const int n = n0 + tx * 8 + jj * 4;
            const float4 bv = *(const float4*)(bias + n);
            float4 v = make_float4(acc[i][jj*4+0] + bv.x, acc[i][jj*4+1] + bv.y,
                                   acc[i][jj*4+2] + bv.z, acc[i][jj*4+3] + bv.w);
            *(float4*)(C + (size_t)m * A_DIM + n) = v;
        }
    }
}

// ---------------- mean over P ----------------
__global__ void mean_k(const float* __restrict__ enc)
{
    const int idx = blockIdx.x * 256 + threadIdx.x;
    const int b = idx >> 11;
    const int e = idx & (ENC - 1);
    const float* p = enc + (size_t)b * P * ENC + e;
    float s = 0.f;
    for (int pp = 0; pp < P; pp++) s += p[(size_t)pp * ENC];
    g_mean[idx] = s * (1.f / (float)P);
}

// ---------------- reduce split-K partials + bias -> out[64, N] ----------
__global__ void reduce_k(const float* __restrict__ part, int nsplit,
                         const float* __restrict__ bias, float* __restrict__ out, int N)
{
    const int idx = blockIdx.x * 256 + threadIdx.x;   // 64*N
    const int b = idx / N;
    const int n = idx - b * N;
    float s = bias[n];
    for (int ss = 0; ss < nsplit; ss++) s += part[(size_t)(ss * 64 + b) * N + n];
    out[idx] = s;
}

// ---------------- fused: att_h reduce + scores + softmax (1 block / b) ----
__global__ void __launch_bounds__(256) scores_k(
    const float* __restrict__ bh, const float* __restrict__ Wa, const float* __restrict__ ba)
{
    __shared__ float sh_h[A_DIM];
    __shared__ float sh_w[A_DIM];
    __shared__ float sc[256];
    const int b = blockIdx.x;
    const int tid = threadIdx.x;

    for (int a = tid; a < A_DIM; a += 256) {
        float s = bh[a];
#pragma unroll
        for (int ss = 0; ss < NS_ATTH; ss++) s += g_part[(size_t)(ss * 64 + b) * A_DIM + a];
        sh_h[a] = s;
        sh_w[a] = Wa[a];
    }
    __syncthreads();

    const int w = tid >> 5, lane = tid & 31;
    for (int p = w; p < P; p += 8) {
        const float* row = g_att_enc + (size_t)(b * P + p) * A_DIM;
        float s = 0.f;
#pragma unroll 4
        for (int a = lane; a < A_DIM; a += 32) {
            float v = row[a] + sh_h[a];
            s += fmaxf(v, 0.f) * sh_w[a];
        }
#pragma unroll
        for (int off = 16; off; off >>= 1) s += __shfl_xor_sync(0xffffffff, s, off);
        if (lane == 0) sc[p] = s + ba[0];
    }
    __syncthreads();

    // softmax over P=196 within the block
    const float v = (tid < P) ? sc[tid] : -FLT_MAX;
    __shared__ float red[256];
    red[tid] = v;
    __syncthreads();
    for (int off = 128; off; off >>= 1) { if (tid < off) red[tid] = fmaxf(red[tid], red[tid + off]); __syncthreads(); }
    const float mx = red[0];
    __syncthreads();
    const float e = (tid < P) ? expf(v - mx) : 0.f;
    red[tid] = e;
    __syncthreads();
    for (int off = 128; off; off >>= 1) { if (tid < off) red[tid] += red[tid + off]; __syncthreads(); }
    const float inv = 1.f / red[0];
    if (tid < P) g_alpha[b * P + tid] = e * inv;
}

// ---------------- weighted = alpha @ encode_out ----------------------------
__global__ void weighted_k(const float* __restrict__ enc)
{
    __shared__ float sa[P];
    const int b = blockIdx.y;
    const int e = blockIdx.x * 256 + threadIdx.x;
    if (threadIdx.x < P) sa[threadIdx.x] = g_alpha[b * P + threadIdx.x];
    __syncthreads();
    const float* base = enc + (size_t)b * P * ENC + e;
    float s = 0.f;
#pragma unroll 4
    for (int p = 0; p < P; p++) s += sa[p] * base[(size_t)p * ENC];
    g_weighted[b * ENC + e] = s;
}

// ---------------- build LSTM input: reduce gate partials + emb gather ------
__global__ void mkinp_k(const float* __restrict__ emb, const int* __restrict__ cap,
                        const float* __restrict__ bg, int t)
{
    const int idx = blockIdx.x * 256 + threadIdx.x;   // 64*(E+ENC)
    const int b = idx / (E + ENC);
    const int j = idx - b * (E + ENC);
    float v;
    if (j < E) {
        const int tok = cap[b * T + t];
        v = emb[(size_t)tok * E + j];
    } else {
        const int j2 = j - E;
        float g = bg[j2];
#pragma unroll
        for (int ss = 0; ss < NS_GATE; ss++) g += g_part[(size_t)(ss * 64 + b) * ENC + j2];
        v = g_weighted[b * ENC + j2] * g;
    }
    g_inp[idx] = v;
}

// ---------------- LSTM cell (reduces gates partials inline) ----------------
__global__ void lstm_k(const float* __restrict__ b_ih, const float* __restrict__ b_hh)
{
    const int idx = blockIdx.x * 256 + threadIdx.x;   // 64*H
    const int b = idx >> 9;
    const int n = idx & (H - 1);
    float gv[4];
#pragma unroll
    for (int q = 0; q < 4; q++) {
        const int pos = q * H + n;
        float s = b_ih[pos] + b_hh[pos];
#pragma unroll
        for (int ss = 0; ss < NS_GATES; ss++) s += g_part[(size_t)(ss * 64 + b) * (4 * H) + pos];
        gv[q] = s;
    }
    const float i_ = sigm(gv[0]);
    const float f_ = sigm(gv[1]);
    const float gg = tanhf(gv[2]);
    const float o_ = sigm(gv[3]);
    const float c  = f_ * g_c[idx] + i_ * gg;
    g_c[idx] = c;
    g_h[idx] = o_ * tanhf(c);
}

// ---------------- zero the final time step ----------------
__global__ void zero_k(float* __restrict__ out)
{
    const int idx = blockIdx.x * 256 + threadIdx.x;
    if (idx < B * V) {
        const int b = idx / V;
        const int n = idx - b * V;
        out[(size_t)b * T * V + (size_t)(T - 1) * V + n] = 0.f;
    }
}

// ---------------- launch ----------------
extern "C" void kernel_launch(void* const* d_in, const int* in_sizes, int n_in,
                              void* d_out, int out_size)
{
    const float* enc  = (const float*)d_in[0];
    const int*   cap  = (const int*)d_in[1];
    const float* emb  = (const float*)d_in[2];
    const float* W_ih = (const float*)d_in[3];
    const float* b_ih = (const float*)d_in[4];
    const float* W_hh = (const float*)d_in[5];
    const float* b_hh = (const float*)d_in[6];
    const float* We   = (const float*)d_in[7];
    const float* be   = (const float*)d_in[8];
    const float* Wh   = (const float*)d_in[9];
    const float* bh   = (const float*)d_in[10];
    const float* Wa   = (const float*)d_in[11];
    const float* ba   = (const float*)d_in[12];
    const float* Wch  = (const float*)d_in[13];
    const float* bch  = (const float*)d_in[14];
    const float* Wcc  = (const float*)d_in[15];
    const float* bcc  = (const float*)d_in[16];
    const float* Wfc  = (const float*)d_in[17];
    const float* bfc  = (const float*)d_in[18];
    const float* Wg   = (const float*)d_in[19];
    const float* bg   = (const float*)d_in[20];
    float* out = (float*)d_out;

    float *p_att_enc, *p_part, *p_mean, *p_h, *p_c, *p_inp;
    cudaGetSymbolAddress((void**)&p_att_enc, g_att_enc);
    cudaGetSymbolAddress((void**)&p_part,    g_part);
    cudaGetSymbolAddress((void**)&p_mean,    g_mean);
    cudaGetSymbolAddress((void**)&p_h,       g_h);
    cudaGetSymbolAddress((void**)&p_c,       g_c);
    cudaGetSymbolAddress((void**)&p_inp,     g_inp);

    // ---- setup ----
    mean_k<<<(B * ENC) / 256, 256>>>(enc);
    // h0: split-K 8 x chunk 256 over K=2048, N=512 -> 8x8=64 blocks, then reduce
    gemm64_k<0><<<dim3(H / 64, NS_HC), 128>>>(p_mean, ENC, nullptr, 0, Wch, ENC, nullptr, 0, 0,
                                              nullptr, p_part, H, H, ENC / NS_HC);
    reduce_k<<<(B * H) / 256, 256>>>(p_part, NS_HC, bch, p_h, H);
    gemm64_k<0><<<dim3(H / 64, NS_HC), 128>>>(p_mean, ENC, nullptr, 0, Wcc, ENC, nullptr, 0, 0,
                                              nullptr, p_part, H, H, ENC / NS_HC);
    reduce_k<<<(B * H) / 256, 256>>>(p_part, NS_HC, bcc, p_c, H);
    // att_enc = encode_out @ We^T + be   (grid 4 x 98 = 392)
    gemm_big_k<<<dim3(A_DIM / 128, (B * P) / 128), 256>>>(enc, We, be, p_att_enc);

    // ---- time loop ----
    for (int t = 0; t < T - 1; t++) {
        // att_h partials: N=512, K=512, chunk 64 -> grid (8, 8) = 64 blocks
        gemm64_k<0><<<dim3(A_DIM / 64, NS_ATTH), 128>>>(p_h, H, nullptr, 0, Wh, H, nullptr, 0, 0,
                                                        nullptr, p_part, A_DIM, A_DIM, H / NS_ATTH);
        // fused reduce + scores + softmax (64 blocks)
        scores_k<<<B, 256>>>(bh, Wa, ba);
        // weighted sum (HBM-bound)
        weighted_k<<<dim3(ENC / 256, B), 256>>>(enc);
        // gate partials: sigmoid(h) @ Wg^T : N=2048, K=512, chunk 128 -> grid (32, 4) = 128
        gemm64_k<1><<<dim3(ENC / 64, NS_GATE), 128>>>(p_h, H, nullptr, 0, Wg, H, nullptr, 0, 0,
                                                      nullptr, p_part, ENC, ENC, H / NS_GATE);
        // inp = [emb gather , weighted * (reduced gate + bg)]
        mkinp_k<<<(B * (E + ENC)) / 256, 256>>>(emb, cap, bg, t);
        // gates partials: dual-region K=3072 (2560 from inp@W_ih, 512 from h@W_hh), chunk 256 -> grid (32, 12) = 384
        gemm64_k<2><<<dim3((4 * H) / 64, NS_GATES), 128>>>(p_inp, E + ENC, p_h, H,
                                                           W_ih, E + ENC, W_hh, H, E + ENC,
                                                           nullptr, p_part, 4 * H, 4 * H, 256);
        // LSTM cell (reduces 12 partials inline)
        lstm_k<<<(B * H) / 256, 256>>>(b_ih, b_hh);
        // pred: N=30000, K=512, no split -> grid (469, 1)
        gemm64_k<0><<<dim3((V + 63) / 64, 1), 128>>>(p_h, H, nullptr, 0, Wfc, H, nullptr, 0, 0,
                                                     bfc, out + (size_t)t * V, (long long)T * V, V, H);
    }
    // out[:, T-1, :] = 0
    zero_k<<<(B * V + 255) / 256, 256>>>(out);
}